// round 17
// baseline (speedup 1.0000x reference)
#include <cuda_runtime.h>
#include <cuda_bf16.h>
#include <cstdint>

#define DD 512
#define NB 8
#define NQ 128
#define NK 256
#define MQ (NB * NQ)            // 1024 query rows
#define MTOT (MQ + NB * NK)     // 3072 total rows
#define OUTN (NB * NQ * NK)     // 262144 output elements

// ---------------------------------------------------------------------------
// Device scratch (graph-capture safe)
// ---------------------------------------------------------------------------
__device__ float g_qt[MQ * DD];               // projected queries (2 MB)
__device__ float g_kt[NB * NK * DD];          // projected keys    (4 MB)
__device__ float g_part[4][OUTN];             // D-split partial scores (4 MB)

__device__ __forceinline__ float fast_tanh(float x) {
    float y;
    asm("tanh.approx.f32 %0, %1;" : "=f"(y) : "f"(x));
    return y;
}

__device__ __forceinline__ void bf16_split(float x, __nv_bfloat16& h, __nv_bfloat16& l) {
    h = __float2bfloat16_rn(x);
    l = __float2bfloat16_rn(x - __bfloat162float(h));
}

#define LDSM4(d0, d1, d2, d3, a)                                               \
    asm volatile("ldmatrix.sync.aligned.m8n8.x4.shared.b16 {%0,%1,%2,%3}, [%4];" \
                 : "=r"(d0), "=r"(d1), "=r"(d2), "=r"(d3) : "r"(a))
#define LDSM2(d0, d1, a)                                                       \
    asm volatile("ldmatrix.sync.aligned.m8n8.x2.shared.b16 {%0,%1}, [%2];"     \
                 : "=r"(d0), "=r"(d1) : "r"(a))

// ---------------------------------------------------------------------------
// Fused projection GEMM (one D-quarter of output columns per launch):
// loads raw f32 X/W, splits to bf16 hi/lo in registers, STS planes, then
// bf16 m16n8k16 3-term compensated MMA. Tile 64x64, grid (48, 2) per launch
// (n-tiles {2*quart, 2*quart+1} -> output columns [128*quart, 128*quart+128)).
// ---------------------------------------------------------------------------
#define BM 64
#define BN 64
#define PKC 32
#define XSTR 40

#define MMA_BF16(c, a, b0_, b1_)                                               \
    asm volatile(                                                              \
        "mma.sync.aligned.m16n8k16.row.col.f32.bf16.bf16.f32 "                 \
        "{%0,%1,%2,%3}, {%4,%5,%6,%7}, {%8,%9}, {%0,%1,%2,%3};"                \
        : "+f"((c)[0]), "+f"((c)[1]), "+f"((c)[2]), "+f"((c)[3])               \
        : "r"((a)[0]), "r"((a)[1]), "r"((a)[2]), "r"((a)[3]),                  \
          "r"(b0_), "r"(b1_))

__global__ __launch_bounds__(256) void proj_fused(
    const float* __restrict__ query, const float* __restrict__ key,
    const float* __restrict__ W1, const float* __restrict__ b1,
    const float* __restrict__ W2, const float* __restrict__ b2,
    int nybase)
{
    __shared__ __nv_bfloat16 sXh[BM * XSTR], sXl[BM * XSTR];
    __shared__ __nv_bfloat16 sWh[BN * XSTR], sWl[BN * XSTR];

    const int m0 = blockIdx.x * BM;
    const int n0 = (nybase + blockIdx.y) * BN;
    const bool isQ = (m0 < MQ);
    const float* Xg = isQ ? (query + (size_t)m0 * DD)
                          : (key + (size_t)(m0 - MQ) * DD);
    const float* Wg = (isQ ? W2 : W1) + (size_t)n0 * DD;
    const float* bias = isQ ? b2 : b1;
    float* out = isQ ? (g_qt + (size_t)m0 * DD) : (g_kt + (size_t)(m0 - MQ) * DD);

    const int tid = threadIdx.x;
    const int wid = tid >> 5, lane = tid & 31;
    const int wm = (wid & 1) * 32;     // 2 warps along m
    const int wn = (wid >> 1) * 16;    // 4 warps along n
    const int gr = lane >> 2;
    const int gc = lane & 3;

    const int grp = lane >> 3, lr = lane & 7;
    const int a_r = (grp & 1) * 8 + lr;
    const int a_c = (grp >> 1) * 8;
    const int b_r = lr;
    const int b_c = (grp & 1) * 8;

    float acc[2][2][4];
#pragma unroll
    for (int mf = 0; mf < 2; mf++)
#pragma unroll
        for (int nf = 0; nf < 2; nf++)
#pragma unroll
            for (int j = 0; j < 4; j++) acc[mf][nf][j] = 0.0f;

    float4 rx[2], rw[2];
    auto prefetch = [&](int kc) {
        const int kb = kc * PKC;
#pragma unroll
        for (int i = 0; i < 2; i++) {
            int idx = tid + i * 256;
            int r = idx >> 3, c4 = (idx & 7) * 4;
            rx[i] = *(const float4*)&Xg[(size_t)r * DD + kb + c4];
            rw[i] = *(const float4*)&Wg[(size_t)r * DD + kb + c4];
        }
    };

    auto commit = [&]() {
#pragma unroll
        for (int i = 0; i < 2; i++) {
            int idx = tid + i * 256;
            int r = idx >> 3, c4 = (idx & 7) * 4;
            int so = r * XSTR + c4;
            __nv_bfloat16 h[4], l[4];
            bf16_split(rx[i].x, h[0], l[0]);
            bf16_split(rx[i].y, h[1], l[1]);
            bf16_split(rx[i].z, h[2], l[2]);
            bf16_split(rx[i].w, h[3], l[3]);
            *(uint2*)&sXh[so] = *(uint2*)h;
            *(uint2*)&sXl[so] = *(uint2*)l;
            bf16_split(rw[i].x, h[0], l[0]);
            bf16_split(rw[i].y, h[1], l[1]);
            bf16_split(rw[i].z, h[2], l[2]);
            bf16_split(rw[i].w, h[3], l[3]);
            *(uint2*)&sWh[so] = *(uint2*)h;
            *(uint2*)&sWl[so] = *(uint2*)l;
        }
    };

    prefetch(0);

    const int NCH = DD / PKC;   // 16
    for (int kc = 0; kc < NCH; kc++) {
        commit();
        __syncthreads();
        if (kc + 1 < NCH) prefetch(kc + 1);

        uint32_t ah[2][2][4], al[2][2][4];
        uint32_t bh[2][2][2], bl[2][2][2];
#pragma unroll
        for (int h = 0; h < 2; h++) {
            const int k16 = h * 16;
#pragma unroll
            for (int mf = 0; mf < 2; mf++) {
                unsigned aoff = (unsigned)((wm + mf * 16 + a_r) * XSTR + k16 + a_c);
                unsigned pah = (unsigned)__cvta_generic_to_shared(&sXh[aoff]);
                unsigned pal = (unsigned)__cvta_generic_to_shared(&sXl[aoff]);
                LDSM4(ah[h][mf][0], ah[h][mf][1], ah[h][mf][2], ah[h][mf][3], pah);
                LDSM4(al[h][mf][0], al[h][mf][1], al[h][mf][2], al[h][mf][3], pal);
            }
#pragma unroll
            for (int nf = 0; nf < 2; nf++) {
                unsigned boff = (unsigned)((wn + nf * 8 + b_r) * XSTR + k16 + b_c);
                unsigned pbh = (unsigned)__cvta_generic_to_shared(&sWh[boff]);
                unsigned pbl = (unsigned)__cvta_generic_to_shared(&sWl[boff]);
                LDSM2(bh[h][nf][0], bh[h][nf][1], pbh);
                LDSM2(bl[h][nf][0], bl[h][nf][1], pbl);
            }
        }
#pragma unroll
        for (int h = 0; h < 2; h++)
#pragma unroll
            for (int nf = 0; nf < 2; nf++)
#pragma unroll
                for (int mf = 0; mf < 2; mf++)
                    MMA_BF16(acc[mf][nf], ah[h][mf], bh[h][nf][0], bh[h][nf][1]);
#pragma unroll
        for (int h = 0; h < 2; h++)
#pragma unroll
            for (int nf = 0; nf < 2; nf++)
#pragma unroll
                for (int mf = 0; mf < 2; mf++)
                    MMA_BF16(acc[mf][nf], al[h][mf], bh[h][nf][0], bh[h][nf][1]);
#pragma unroll
        for (int h = 0; h < 2; h++)
#pragma unroll
            for (int nf = 0; nf < 2; nf++)
#pragma unroll
                for (int mf = 0; mf < 2; mf++)
                    MMA_BF16(acc[mf][nf], ah[h][mf], bl[h][nf][0], bl[h][nf][1]);
        __syncthreads();
    }

#pragma unroll
    for (int nf = 0; nf < 2; nf++) {
        int col = wn + nf * 8 + 2 * gc;
        float2 bb = *(const float2*)&bias[n0 + col];
#pragma unroll
        for (int mf = 0; mf < 2; mf++) {
            int row = wm + mf * 16 + gr;
            float2 o0, o1;
            o0.x = acc[mf][nf][0] + bb.x;  o0.y = acc[mf][nf][1] + bb.y;
            o1.x = acc[mf][nf][2] + bb.x;  o1.y = acc[mf][nf][3] + bb.y;
            *(float2*)&out[row * DD + n0 + col] = o0;
            *(float2*)&out[(row + 8) * DD + n0 + col] = o1;
        }
    }
}

// ---------------------------------------------------------------------------
// Score (one D-quarter per launch): partial[b,q,k] = sum_d v[d]*tanh(qt+kt)
// Tile 16q x 32k x 128d, 128 threads, 2x2 micro-tile, 512 blocks per quarter.
// ---------------------------------------------------------------------------
#define SQ 16
#define SK 32
#define SD 64
#define DQUART 128

__global__ __launch_bounds__(128) void score_kernel(
    const float* __restrict__ v, int quart)
{
    __shared__ float qs[SQ][68];      // q-major
    __shared__ float ks[SD][34];      // dd-major (transposed)
    __shared__ float vs[DQUART];

    const int b   = blockIdx.z;
    const int dcb = quart * DQUART;
    const int q0 = blockIdx.y * SQ;
    const int k0 = blockIdx.x * SK;
    const float* qt = g_qt + ((size_t)b * NQ + q0) * DD;
    const float* kt = g_kt + ((size_t)b * NK + k0) * DD;
    float* po = g_part[quart];

    const int tid = threadIdx.x;
    const int tk = tid & 15;
    const int tq = tid >> 4;

    vs[tid] = v[dcb + tid];

    float a00 = 0.f, a01 = 0.f, a10 = 0.f, a11 = 0.f;

    for (int dl = 0; dl < DQUART; dl += SD) {
        const int dc = dcb + dl;
#pragma unroll
        for (int i = 0; i < 2; i++) {
            int idx = tid + i * 128;
            int r = idx >> 4, c4 = (idx & 15) * 4;
            float4 t = *(const float4*)&qt[r * DD + dc + c4];
            *(float4*)&qs[r][c4] = t;
        }
#pragma unroll
        for (int i = 0; i < 4; i++) {
            int idx = tid + i * 128;
            int r = idx >> 4, c4 = (idx & 15) * 4;
            float4 t = *(const float4*)&kt[r * DD + dc + c4];
            ks[c4 + 0][r] = t.x;
            ks[c4 + 1][r] = t.y;
            ks[c4 + 2][r] = t.z;
            ks[c4 + 3][r] = t.w;
        }
        __syncthreads();

#pragma unroll
        for (int d4 = 0; d4 < SD; d4 += 4) {
            float4 q0v = *(const float4*)&qs[tq * 2 + 0][d4];
            float4 q1v = *(const float4*)&qs[tq * 2 + 1][d4];
            float2 kk0 = *(const float2*)&ks[d4 + 0][tk * 2];
            float2 kk1 = *(const float2*)&ks[d4 + 1][tk * 2];
            float2 kk2 = *(const float2*)&ks[d4 + 2][tk * 2];
            float2 kk3 = *(const float2*)&ks[d4 + 3][tk * 2];
            float4 vv  = *(const float4*)&vs[dl + d4];

            a00 = fmaf(vv.x, fast_tanh(q0v.x + kk0.x), a00);
            a01 = fmaf(vv.x, fast_tanh(q0v.x + kk0.y), a01);
            a10 = fmaf(vv.x, fast_tanh(q1v.x + kk0.x), a10);
            a11 = fmaf(vv.x, fast_tanh(q1v.x + kk0.y), a11);

            a00 = fmaf(vv.y, fast_tanh(q0v.y + kk1.x), a00);
            a01 = fmaf(vv.y, fast_tanh(q0v.y + kk1.y), a01);
            a10 = fmaf(vv.y, fast_tanh(q1v.y + kk1.x), a10);
            a11 = fmaf(vv.y, fast_tanh(q1v.y + kk1.y), a11);

            a00 = fmaf(vv.z, fast_tanh(q0v.z + kk2.x), a00);
            a01 = fmaf(vv.z, fast_tanh(q0v.z + kk2.y), a01);
            a10 = fmaf(vv.z, fast_tanh(q1v.z + kk2.x), a10);
            a11 = fmaf(vv.z, fast_tanh(q1v.z + kk2.y), a11);

            a00 = fmaf(vv.w, fast_tanh(q0v.w + kk3.x), a00);
            a01 = fmaf(vv.w, fast_tanh(q0v.w + kk3.y), a01);
            a10 = fmaf(vv.w, fast_tanh(q1v.w + kk3.x), a10);
            a11 = fmaf(vv.w, fast_tanh(q1v.w + kk3.y), a11);
        }
        __syncthreads();
    }

    {
        float2 o0; o0.x = a00; o0.y = a01;
        float2 o1; o1.x = a10; o1.y = a11;
        *(float2*)&po[((size_t)b * NQ + q0 + tq * 2 + 0) * NK + k0 + tk * 2] = o0;
        *(float2*)&po[((size_t)b * NQ + q0 + tq * 2 + 1) * NK + k0 + tk * 2] = o1;
    }
}

// ---------------------------------------------------------------------------
// Combine: out = part0 + part1 + part2 + part3  (65536 float4)
// ---------------------------------------------------------------------------
__global__ __launch_bounds__(256) void combine_kernel(float4* __restrict__ out)
{
    int idx = blockIdx.x * 1024 + threadIdx.x;
    const float4* p0 = (const float4*)g_part[0];
    const float4* p1 = (const float4*)g_part[1];
    const float4* p2 = (const float4*)g_part[2];
    const float4* p3 = (const float4*)g_part[3];
#pragma unroll
    for (int i = 0; i < 4; i++) {
        int j = idx + i * 256;
        float4 a = p0[j], b = p1[j], c = p2[j], d = p3[j];
        float4 o;
        o.x = (a.x + b.x) + (c.x + d.x);
        o.y = (a.y + b.y) + (c.y + d.y);
        o.z = (a.z + b.z) + (c.z + d.z);
        o.w = (a.w + b.w) + (c.w + d.w);
        out[j] = o;
    }
}

extern "C" void kernel_launch(void* const* d_in, const int* in_sizes, int n_in,
                              void* d_out, int out_size)
{
    const float* query = (const float*)d_in[0];  // [8,128,512]
    const float* key   = (const float*)d_in[1];  // [8,256,512]
    const float* W1    = (const float*)d_in[2];  // [512,512]
    const float* b1    = (const float*)d_in[3];  // [512]
    const float* W2    = (const float*)d_in[4];  // [512,512]
    const float* b2    = (const float*)d_in[5];  // [512]
    const float* v     = (const float*)d_in[6];  // [512]
    float* out = (float*)d_out;                  // [8,128,256]

    // Stream/events created on the (uncaptured) correctness call; reused in
    // capture via the standard event-fork pattern. No device memory involved.
    static cudaStream_t s2 = nullptr;
    static cudaEvent_t ev_p[4], ev_s;
    if (!s2) {
        cudaStreamCreateWithFlags(&s2, cudaStreamNonBlocking);
        for (int i = 0; i < 4; i++)
            cudaEventCreateWithFlags(&ev_p[i], cudaEventDisableTiming);
        cudaEventCreateWithFlags(&ev_s, cudaEventDisableTiming);
    }

    // Pipelined overlap across the column-partitioned proj->score dependency:
    //   main stream: P0 P1 P2 P3 ... combine
    //   s2:          (after Pi) Si                  i = 0..3
    for (int i = 0; i < 4; i++) {
        // proj quarter i: n-tiles {2i, 2i+1} -> q_t/k_t columns [128i,128i+128)
        proj_fused<<<dim3(48, 2), 256>>>(query, key, W1, b1, W2, b2, 2 * i);
        cudaEventRecord(ev_p[i], 0);
        cudaStreamWaitEvent(s2, ev_p[i], 0);
        // score quarter i reads exactly those columns: 8x8x8 = 512 blocks
        score_kernel<<<dim3(NK / SK, NQ / SQ, NB), 128, 0, s2>>>(v, i);
    }
    cudaEventRecord(ev_s, s2);
    cudaStreamWaitEvent(0, ev_s, 0);
    combine_kernel<<<64, 256>>>((float4*)out);
}